// round 2
// baseline (speedup 1.0000x reference)
#include <cuda_runtime.h>
#include <cstdint>
#include <cstddef>
#include <math.h>

typedef unsigned long long ull;

#define B_   256
#define T_   512
#define E_   128
#define H_   512
#define A_   10
#define KZ   768      // H + 2E
#define NBLK 128      // persistent blocks (<= 148 SMs -> all resident in one wave)
#define JPB  4        // hidden units per block (NBLK*JPB == H)

// ---------------- scratch (__device__ globals: the sanctioned no-alloc path) ----
__device__ float    g_ctxT[(size_t)T_ * E_ * B_];   // [t][e][b]  64 MB
__device__ float    g_x1T [(size_t)T_ * E_ * B_];   // [t][e][b]  64 MB
__device__ float    g_hbuf[2 * H_ * B_];            // double-buffered h, [buf][k][b]
__device__ float    g_hs  [(size_t)T_ * H_ * B_];   // [t][j][b]  256 MB
__device__ unsigned g_flags[NBLK];
__device__ unsigned g_release;

// ---------------- packed f32x2 helpers ----------------------------------------
__device__ __forceinline__ ull pk2(float x) {
    ull r; unsigned u = __float_as_uint(x);
    asm("mov.b64 %0, {%1, %1};" : "=l"(r) : "r"(u));
    return r;
}
__device__ __forceinline__ ull pkp(float x, float y) {
    ull r;
    asm("mov.b64 %0, {%1, %2};" : "=l"(r)
        : "r"(__float_as_uint(x)), "r"(__float_as_uint(y)));
    return r;
}
__device__ __forceinline__ float2 unpk(ull v) {
    unsigned lo, hi;
    asm("mov.b64 {%0, %1}, %2;" : "=r"(lo), "=r"(hi) : "l"(v));
    return make_float2(__uint_as_float(lo), __uint_as_float(hi));
}
__device__ __forceinline__ void fma2(ull &d, ull a, ull b) {
    asm("fma.rn.f32x2 %0, %1, %2, %3;" : "=l"(d) : "l"(a), "l"(b), "l"(d));
}
__device__ __forceinline__ float sigm(float x) { return 1.0f / (1.0f + expf(-x)); }

// ---------------- reset: zero h buffer 0 + barrier state -----------------------
__global__ void reset_kernel() {
    int i = blockIdx.x * 256 + threadIdx.x;          // grid 512 x 256 = 131072
    if (i < H_ * B_) g_hbuf[i] = 0.0f;               // buffer 0 only (buf 1 is
    if (i < NBLK)    g_flags[i] = 0u;                //  fully written before read)
    if (i == NBLK)   g_release = 0u;
}

// ---------------- x1 transpose: [b][t][e] -> [t][e][b] -------------------------
__global__ void transpose_x1(const float* __restrict__ x1) {
    __shared__ float tile[32][33];
    int t  = blockIdx.z;
    int e0 = blockIdx.x * 32;
    int b0 = blockIdx.y * 32;
    int tx = threadIdx.x, ty = threadIdx.y;          // block (32, 8)
#pragma unroll
    for (int r = 0; r < 4; r++) {
        int b = b0 + ty + 8 * r;
        tile[ty + 8 * r][tx] = x1[((size_t)b * T_ + t) * E_ + e0 + tx];
    }
    __syncthreads();
#pragma unroll
    for (int r = 0; r < 4; r++) {
        int e = e0 + ty + 8 * r;
        g_x1T[((size_t)t * E_ + e) * B_ + b0 + tx] = tile[tx][ty + 8 * r];
    }
}

// ---------------- attention + context precompute -------------------------------
// softmax over 'a' is invariant to the hx1@w_attn_h term (constant over a),
// so attention depends only on x2 -> fully parallel precompute.
__global__ void attn_ctx(const float* __restrict__ x2, const float* __restrict__ Wa) {
    int wg   = blockIdx.x * 8 + (threadIdx.x >> 5);  // warp per (b,t); wg = b*T + t
    int lane = threadIdx.x & 31;
    int b = wg >> 9;        // / 512
    int t = wg & 511;
    const float* xp = x2 + (size_t)wg * (A_ * E_);

    float w2v[4];
#pragma unroll
    for (int i = 0; i < 4; i++) w2v[i] = Wa[(H_ + E_) + lane + 32 * i];

    float s[A_];
#pragma unroll
    for (int a = 0; a < A_; a++) {
        const float* xa = xp + a * E_;
        float p = 0.0f;
#pragma unroll
        for (int i = 0; i < 4; i++) p += xa[lane + 32 * i] * w2v[i];
#pragma unroll
        for (int off = 16; off; off >>= 1) p += __shfl_xor_sync(0xffffffffu, p, off);
        s[a] = p;
    }
    float m = s[0];
#pragma unroll
    for (int a = 1; a < A_; a++) m = fmaxf(m, s[a]);
    float den = 0.0f;
#pragma unroll
    for (int a = 0; a < A_; a++) { s[a] = expf(s[a] - m); den += s[a]; }
    float inv = 1.0f / den;
#pragma unroll
    for (int i = 0; i < 4; i++) {
        int e = lane + 32 * i;
        float cv = 0.0f;
#pragma unroll
        for (int a = 0; a < A_; a++) cv += s[a] * xp[a * E_ + e];
        g_ctxT[((size_t)t * E_ + e) * B_ + b] = cv * inv;
    }
}

// ---------------- persistent LSTM recurrence -----------------------------------
__global__ void __launch_bounds__(256, 1)
lstm_persist(const int* __restrict__ seq,
             const float* __restrict__ Wf, const float* __restrict__ bf,
             const float* __restrict__ Wi, const float* __restrict__ bi,
             const float* __restrict__ Wc, const float* __restrict__ bc,
             const float* __restrict__ Wo, const float* __restrict__ bo)
{
    __shared__ float sw[KZ * 16];                    // 48 KB: 768 x (4 units x 4 gates)
    const int tid = threadIdx.x;
    const int bid = blockIdx.x;
    const int j0  = bid * JPB;

    {   // weight slice load, gate order f,i,c,o interleaved per unit
        const float* Wg[4] = {Wf, Wi, Wc, Wo};
        for (int lin = tid; lin < KZ * 16; lin += 256) {
            int k = lin >> 4, idx = lin & 15;
            sw[lin] = Wg[idx & 3][k * H_ + j0 + (idx >> 2)];
        }
    }
    float bsv[16];
    {
        const float* bg[4] = {bf, bi, bc, bo};
#pragma unroll
        for (int p = 0; p < 16; p++) bsv[p] = bg[p & 3][j0 + (p >> 2)];
    }
    ull bias2[8];
#pragma unroll
    for (int p = 0; p < 8; p++) bias2[p] = pkp(bsv[2 * p], bsv[2 * p + 1]);

    const int b   = tid;
    const int len = seq[b];
    float hReg[JPB] = {0, 0, 0, 0};
    float cReg[JPB] = {0, 0, 0, 0};
    __syncthreads();

    const ulonglong2* sw8 = reinterpret_cast<const ulonglong2*>(sw);
    volatile unsigned* vf  = (volatile unsigned*)g_flags;
    volatile unsigned* vrel = (volatile unsigned*)&g_release;

    for (int t = 0; t < T_; t++) {
        const bool active = (t < len);
        const unsigned amask = __ballot_sync(0xffffffffu, active);

        if (amask) {
            ull a0 = bias2[0], a1 = bias2[1], a2 = bias2[2], a3 = bias2[3];
            ull a4 = bias2[4], a5 = bias2[5], a6 = bias2[6], a7 = bias2[7];

#define DOK(KIDX, ZV) do {                                                     \
            ull zz = pk2(ZV);                                                  \
            const ulonglong2* wp = sw8 + (size_t)(KIDX) * 4;                   \
            ulonglong2 q0 = wp[0], q1 = wp[1], q2 = wp[2], q3 = wp[3];         \
            fma2(a0, zz, q0.x); fma2(a1, zz, q0.y);                            \
            fma2(a2, zz, q1.x); fma2(a3, zz, q1.y);                            \
            fma2(a4, zz, q2.x); fma2(a5, zz, q2.y);                            \
            fma2(a6, zz, q3.x); fma2(a7, zz, q3.y); } while (0)

            const float* hb = g_hbuf + (t & 1) * (H_ * B_) + b;
#pragma unroll 4
            for (int k = 0; k < H_; k++) {
                float z = __ldcg(hb + k * B_);       // L2 path: dodge stale L1
                DOK(k, z);
            }
            const float* xp = g_x1T + (size_t)t * (E_ * B_) + b;
#pragma unroll 4
            for (int e = 0; e < E_; e++) { float z = xp[(size_t)e * B_]; DOK(H_ + e, z); }
            const float* cp = g_ctxT + (size_t)t * (E_ * B_) + b;
#pragma unroll 4
            for (int e = 0; e < E_; e++) { float z = cp[(size_t)e * B_]; DOK(H_ + E_ + e, z); }
#undef DOK

            if (active) {
                ull accs[8] = {a0, a1, a2, a3, a4, a5, a6, a7};
#pragma unroll
                for (int u = 0; u < JPB; u++) {
                    float2 fi = unpk(accs[2 * u]);
                    float2 co = unpk(accs[2 * u + 1]);
                    float fg = sigm(fi.x);
                    float ig = sigm(fi.y);
                    float gg = tanhf(co.x);
                    float og = sigm(co.y);
                    cReg[u] = fg * cReg[u] + ig * gg;
                    hReg[u] = og * tanhf(cReg[u]);
                }
            }
        }

        // publish h (double buffer) + history (masked rows contribute zeros)
        float* hb2 = g_hbuf + ((t + 1) & 1) * (H_ * B_);
        float* hsP = g_hs + ((size_t)t * H_ + j0) * B_ + b;
#pragma unroll
        for (int u = 0; u < JPB; u++) {
            hb2[(j0 + u) * B_ + b] = hReg[u];
            hsP[(size_t)u * B_]    = active ? hReg[u] : 0.0f;
        }

        // ---- software grid barrier (all 128 blocks resident) ----
        __threadfence();
        __syncthreads();
        if (tid == 0) vf[bid] = (unsigned)(t + 1);
        if (bid == 0) {
            if (tid < NBLK) {
                while (vf[tid] < (unsigned)(t + 1)) { __nanosleep(20); }
            }
            __syncthreads();
            if (tid == 0) { __threadfence(); *vrel = (unsigned)(t + 1); }
        } else {
            if (tid == 0) {
                while (*vrel < (unsigned)(t + 1)) { __nanosleep(20); }
            }
            __syncthreads();
        }
    }
}

// ---------------- output GEMM: out[b][t][e] = hs[t][:][b] . W_lin + b_lin ------
__global__ void out_gemm(const float* __restrict__ Wl,
                         const float* __restrict__ bl,
                         float* __restrict__ out)
{
    const int t  = blockIdx.x;
    const int b0 = blockIdx.y * 64;
    __shared__ float sa[16][64];     // hs  [k][b]
    __shared__ float sb[16][128];    // Wl  [k][e]
    const int tid = threadIdx.x;
    const int bg  = tid >> 4;        // 0..15 -> 4 batch rows each
    const int eg  = tid & 15;        // 0..15 -> 8 e cols each

    float acc[4][8];
#pragma unroll
    for (int u = 0; u < 4; u++)
#pragma unroll
        for (int j = 0; j < 8; j++) acc[u][j] = 0.0f;

    for (int k0 = 0; k0 < H_; k0 += 16) {
        for (int i = tid; i < 16 * 64; i += 256) {
            int kk = i >> 6, bb = i & 63;
            sa[kk][bb] = g_hs[((size_t)t * H_ + k0 + kk) * B_ + b0 + bb];
        }
        for (int i = tid; i < 16 * 128; i += 256) {
            int kk = i >> 7, ee = i & 127;
            sb[kk][ee] = Wl[(k0 + kk) * E_ + ee];
        }
        __syncthreads();
#pragma unroll
        for (int kk = 0; kk < 16; kk++) {
            float av[4], wv[8];
#pragma unroll
            for (int u = 0; u < 4; u++) av[u] = sa[kk][bg * 4 + u];
#pragma unroll
            for (int j = 0; j < 8; j++) wv[j] = sb[kk][eg * 8 + j];
#pragma unroll
            for (int u = 0; u < 4; u++)
#pragma unroll
                for (int j = 0; j < 8; j++) acc[u][j] += av[u] * wv[j];
        }
        __syncthreads();
    }
#pragma unroll
    for (int u = 0; u < 4; u++) {
        int b = b0 + bg * 4 + u;
#pragma unroll
        for (int j = 0; j < 8; j++) {
            int e = eg * 8 + j;
            out[((size_t)b * T_ + t) * E_ + e] = acc[u][j] + bl[e];
        }
    }
}

// ---------------- launch -------------------------------------------------------
extern "C" void kernel_launch(void* const* d_in, const int* in_sizes, int n_in,
                              void* d_out, int out_size)
{
    const float* x1 = (const float*)d_in[0];
    const float* x2 = (const float*)d_in[1];
    const int*   sq = (const int*)  d_in[2];
    const float* Wf = (const float*)d_in[3];
    const float* bf = (const float*)d_in[4];
    const float* Wi = (const float*)d_in[5];
    const float* bi = (const float*)d_in[6];
    const float* Wc = (const float*)d_in[7];
    const float* bc = (const float*)d_in[8];
    const float* Wo = (const float*)d_in[9];
    const float* bo = (const float*)d_in[10];
    const float* Wa = (const float*)d_in[11];
    const float* Wl = (const float*)d_in[12];
    const float* bl = (const float*)d_in[13];
    float* out = (float*)d_out;

    reset_kernel<<<512, 256>>>();
    transpose_x1<<<dim3(E_ / 32, B_ / 32, T_), dim3(32, 8)>>>(x1);
    attn_ctx<<<(B_ * T_) / 8, 256>>>(x2, Wa);
    lstm_persist<<<NBLK, 256>>>(sq, Wf, bf, Wi, bi, Wc, bc, Wo, bo);
    out_gemm<<<dim3(T_, B_ / 64), 256>>>(Wl, bl, out);
}

// round 3
// speedup vs baseline: 1.8768x; 1.8768x over previous
#include <cuda_runtime.h>
#include <cstdint>
#include <cstddef>
#include <math.h>

typedef unsigned long long ull;

#define B_    256
#define T_    512
#define E_    128
#define H_    512
#define A_    10
#define ZK    256          // x-part K = 2E
#define GC    2048         // 4H interleaved gate columns (col 4u+g: g=0 f,1 i,2 c,3 o)
#define NBLK  128
#define HB    (H_ * B_)

// ---------------- device-global scratch ----------------------------------------
__device__ float    g_zxT [(size_t)T_ * 256 * B_];   // [t][e(0..255)][b]  (x1 | ctx)
__device__ float    g_Wh  [(size_t)H_ * GC];         // [k][j]
__device__ float    g_Wx  [(size_t)ZK * GC];         // [e][j]
__device__ float    g_bias[GC];
__device__ float    g_xp  [(size_t)T_ * GC * B_];    // [t][j][b]  bias + xpart
__device__ float    g_hbuf[2 * HB];                  // [buf][k][b]
__device__ float    g_hs  [(size_t)T_ * H_ * B_];    // [t][u][b]
__device__ unsigned g_flags[NBLK];
__device__ unsigned g_release;

// ---------------- helpers -------------------------------------------------------
__device__ __forceinline__ ull pk2(float x) {
    ull r; asm("mov.b64 %0, {%1, %1};" : "=l"(r) : "r"(__float_as_uint(x))); return r;
}
__device__ __forceinline__ ull pkp(float x, float y) {
    ull r; asm("mov.b64 %0, {%1, %2};" : "=l"(r)
               : "r"(__float_as_uint(x)), "r"(__float_as_uint(y))); return r;
}
__device__ __forceinline__ float2 unpk(ull v) {
    unsigned lo, hi; asm("mov.b64 {%0, %1}, %2;" : "=r"(lo), "=r"(hi) : "l"(v));
    return make_float2(__uint_as_float(lo), __uint_as_float(hi));
}
__device__ __forceinline__ void fma2(ull &d, ull a, ull b) {
    asm("fma.rn.f32x2 %0, %1, %2, %3;" : "=l"(d) : "l"(a), "l"(b), "l"(d));
}
__device__ __forceinline__ float sigm(float x) { return 1.0f / (1.0f + __expf(-x)); }

__device__ __forceinline__ void cp16(void* dst, const void* src) {
    unsigned d = (unsigned)__cvta_generic_to_shared(dst);
    asm volatile("cp.async.ca.shared.global [%0], [%1], 16;" :: "r"(d), "l"(src));
}
__device__ __forceinline__ void cp_commit() { asm volatile("cp.async.commit_group;"); }
__device__ __forceinline__ void cp_wait1()  { asm volatile("cp.async.wait_group 1;"); }
__device__ __forceinline__ void cp_wait0()  { asm volatile("cp.async.wait_group 0;"); }

// ---------------- reset: zero g_hs + hbuf buf0 + barrier state ------------------
__global__ void reset_kernel() {
    size_t gid = (size_t)blockIdx.x * 256 + threadIdx.x;   // grid 65536 x 256
    float4 z4 = make_float4(0.f, 0.f, 0.f, 0.f);
    ((float4*)g_hs)[gid] = z4;                             // 16,777,216 * 4 floats exact
    if (gid < HB / 4) ((float4*)g_hbuf)[gid] = z4;
    if (gid < NBLK)   g_flags[gid] = 0u;
    if (gid == NBLK)  g_release = 0u;
}

// ---------------- weight prep: interleave gates ---------------------------------
__global__ void weight_prep(const float* __restrict__ Wf, const float* __restrict__ bf,
                            const float* __restrict__ Wi, const float* __restrict__ bi,
                            const float* __restrict__ Wc, const float* __restrict__ bc,
                            const float* __restrict__ Wo, const float* __restrict__ bo)
{
    int idx = blockIdx.x * 256 + threadIdx.x;              // grid 6144
    if (idx < 768 * GC) {
        int k = idx >> 11, j = idx & (GC - 1);
        int u = j >> 2, g = j & 3;
        const float* W = (g == 0) ? Wf : (g == 1) ? Wi : (g == 2) ? Wc : Wo;
        float v = W[k * H_ + u];
        if (k < H_) g_Wh[(size_t)k * GC + j] = v;
        else        g_Wx[(size_t)(k - H_) * GC + j] = v;
    }
    if (idx < GC) {
        int u = idx >> 2, g = idx & 3;
        const float* bb = (g == 0) ? bf : (g == 1) ? bi : (g == 2) ? bc : bo;
        g_bias[idx] = bb[u];
    }
}

// ---------------- x1 transpose: [b][t][e] -> g_zxT[t][e][b] ---------------------
__global__ void transpose_x1(const float* __restrict__ x1, const int* __restrict__ seq) {
    __shared__ float tile[32][33];
    int t  = blockIdx.z;
    int e0 = blockIdx.x * 32;
    int b0 = blockIdx.y * 32;
    if (t >= __ldg(&seq[b0])) return;                      // sorted desc: max of tile
    int tx = threadIdx.x, ty = threadIdx.y;                // block (32, 8)
#pragma unroll
    for (int r = 0; r < 4; r++) {
        int b = b0 + ty + 8 * r;
        tile[ty + 8 * r][tx] = x1[((size_t)b * T_ + t) * E_ + e0 + tx];
    }
    __syncthreads();
#pragma unroll
    for (int r = 0; r < 4; r++) {
        int e = e0 + ty + 8 * r;
        g_zxT[((size_t)t * 256 + e) * B_ + b0 + tx] = tile[tx][ty + 8 * r];
    }
}

// ---------------- attention + context precompute --------------------------------
// softmax over 'a' is invariant to the h-term (constant over a) => h-independent.
__global__ void attn_ctx(const float* __restrict__ x2, const float* __restrict__ Wa,
                         const int* __restrict__ seq) {
    int wg   = blockIdx.x * 8 + (threadIdx.x >> 5);        // warp per (b,t)
    int lane = threadIdx.x & 31;
    int b = wg >> 9, t = wg & 511;
    if (t >= __ldg(&seq[b])) return;
    const float* xp = x2 + (size_t)wg * (A_ * E_);

    float w2v[4];
#pragma unroll
    for (int i = 0; i < 4; i++) w2v[i] = Wa[(H_ + E_) + lane + 32 * i];

    float s[A_];
#pragma unroll
    for (int a = 0; a < A_; a++) {
        const float* xa = xp + a * E_;
        float p = 0.0f;
#pragma unroll
        for (int i = 0; i < 4; i++) p += xa[lane + 32 * i] * w2v[i];
#pragma unroll
        for (int off = 16; off; off >>= 1) p += __shfl_xor_sync(0xffffffffu, p, off);
        s[a] = p;
    }
    float m = s[0];
#pragma unroll
    for (int a = 1; a < A_; a++) m = fmaxf(m, s[a]);
    float den = 0.0f;
#pragma unroll
    for (int a = 0; a < A_; a++) { s[a] = __expf(s[a] - m); den += s[a]; }
    float inv = 1.0f / den;
#pragma unroll
    for (int i = 0; i < 4; i++) {
        int e = lane + 32 * i;
        float cv = 0.0f;
#pragma unroll
        for (int a = 0; a < A_; a++) cv += s[a] * xp[a * E_ + e];
        g_zxT[((size_t)t * 256 + 128 + e) * B_ + b] = cv * inv;
    }
}

// ---------------- x-part GEMM: g_xp[t][j][b] = bias + [x1,ctx] @ Wx -------------
__global__ void __launch_bounds__(256) xpart_gemm(const int* __restrict__ seq) {
    const int jt = blockIdx.x, bt = blockIdx.y, t = blockIdx.z;
    const int j0 = jt * 64, b0 = bt * 64;
    if (t >= __ldg(&seq[b0])) return;

    __shared__ float sa[2][32][64];
    __shared__ float sb[2][32][64];
    const int tid = threadIdx.x;
    const int tx = tid & 15, ty = tid >> 4;
    const int kk = tid >> 3, r8 = (tid & 7) * 8;

    const float* zsrc = g_zxT + (size_t)t * 256 * B_ + b0;

#define STAGE(c, buf) do {                                                     \
        const float* s1 = zsrc + (size_t)((c) * 32 + kk) * B_ + r8;            \
        cp16(&sa[buf][kk][r8], s1); cp16(&sa[buf][kk][r8 + 4], s1 + 4);        \
        const float* s2 = g_Wx + (size_t)((c) * 32 + kk) * GC + j0 + r8;       \
        cp16(&sb[buf][kk][r8], s2); cp16(&sb[buf][kk][r8 + 4], s2 + 4);        \
        cp_commit(); } while (0)

    float4 bq = *(const float4*)&g_bias[j0 + 4 * tx];
    ull acc[4][2];
    ull bfi = pkp(bq.x, bq.y), bco = pkp(bq.z, bq.w);
#pragma unroll
    for (int r = 0; r < 4; r++) { acc[r][0] = bfi; acc[r][1] = bco; }

    STAGE(0, 0);
    for (int c = 0; c < 8; c++) {
        if (c < 7) { STAGE(c + 1, (c + 1) & 1); cp_wait1(); } else cp_wait0();
        __syncthreads();
        const int buf = c & 1;
#pragma unroll 8
        for (int k2 = 0; k2 < 32; k2++) {
            float4 zq = *(const float4*)&sa[buf][k2][4 * ty];
            ulonglong2 wq = *(const ulonglong2*)&sb[buf][k2][4 * tx];
            ull z0 = pk2(zq.x), z1 = pk2(zq.y), z2 = pk2(zq.z), z3 = pk2(zq.w);
            fma2(acc[0][0], z0, wq.x); fma2(acc[0][1], z0, wq.y);
            fma2(acc[1][0], z1, wq.x); fma2(acc[1][1], z1, wq.y);
            fma2(acc[2][0], z2, wq.x); fma2(acc[2][1], z2, wq.y);
            fma2(acc[3][0], z3, wq.x); fma2(acc[3][1], z3, wq.y);
        }
        __syncthreads();
    }
#undef STAGE
    float2 p0 = unpk(acc[0][0]), q0 = unpk(acc[0][1]);
    float2 p1 = unpk(acc[1][0]), q1 = unpk(acc[1][1]);
    float2 p2 = unpk(acc[2][0]), q2 = unpk(acc[2][1]);
    float2 p3 = unpk(acc[3][0]), q3 = unpk(acc[3][1]);
    float* op = g_xp + ((size_t)t * GC + j0 + 4 * tx) * B_ + b0 + 4 * ty;
    *(float4*)(op)           = make_float4(p0.x, p1.x, p2.x, p3.x);
    *(float4*)(op + B_)      = make_float4(p0.y, p1.y, p2.y, p3.y);
    *(float4*)(op + 2 * B_)  = make_float4(q0.x, q1.x, q2.x, q3.x);
    *(float4*)(op + 3 * B_)  = make_float4(q0.y, q1.y, q2.y, q3.y);
}

// ---------------- persistent LSTM recurrence (h @ Wh only) ----------------------
// 128 blocks = 4 batch-tiles x 32 col-tiles, one wave. Wh slice resident in smem.
__global__ void __launch_bounds__(256, 1)
lstm_persist(const int* __restrict__ seq)
{
    extern __shared__ float dsm[];
    float* sw = dsm;                       // [512][64]   128 KB
    float* sz = dsm + H_ * 64;             // [2][32][128] 32 KB (duplicated pairs)

    const int tid = threadIdx.x, bid = blockIdx.x;
    const int ct = bid & 31, bt = bid >> 5;
    const int j0 = ct * 64, b0 = bt * 64;
    const int tx = tid & 15, ty = tid >> 4;
    const int u  = ct * 16 + tx;
    const int kkt = tid >> 3, r8 = (tid & 7) * 8;

    for (int i4 = tid * 4; i4 < H_ * 64; i4 += 256 * 4) {
        int k = i4 >> 6, c = i4 & 63;
        *(float4*)&sw[i4] = *(const float4*)&g_Wh[(size_t)k * GC + j0 + c];
    }
    int len[4];
#pragma unroll
    for (int r = 0; r < 4; r++) len[r] = __ldg(&seq[b0 + 4 * ty + r]);
    const int tile_len = __ldg(&seq[b0]);   // sorted desc -> tile max
    float cc[4] = {0, 0, 0, 0}, hh[4] = {0, 0, 0, 0};
    __syncthreads();

    volatile unsigned* vf   = (volatile unsigned*)g_flags;
    volatile unsigned* vrel = (volatile unsigned*)&g_release;

    for (int t = 0; t < T_; t++) {
        if (t < tile_len) {
            const float* hbase = g_hbuf + (t & 1) * HB + b0;
            // prefetch chunk0 + xpart (acc init)
            const float* s00 = hbase + (size_t)kkt * B_ + r8;
            float4 s0 = __ldcg((const float4*)s00);
            float4 s1 = __ldcg((const float4*)(s00 + 4));
            const float* xpb = g_xp + ((size_t)t * GC + j0 + 4 * tx) * B_ + b0 + 4 * ty;
            float4 xq0 = __ldg((const float4*)xpb);
            float4 xq1 = __ldg((const float4*)(xpb + B_));
            float4 xq2 = __ldg((const float4*)(xpb + 2 * B_));
            float4 xq3 = __ldg((const float4*)(xpb + 3 * B_));
            ull acc[4][2];
            acc[0][0] = pkp(xq0.x, xq1.x); acc[0][1] = pkp(xq2.x, xq3.x);
            acc[1][0] = pkp(xq0.y, xq1.y); acc[1][1] = pkp(xq2.y, xq3.y);
            acc[2][0] = pkp(xq0.z, xq1.z); acc[2][1] = pkp(xq2.z, xq3.z);
            acc[3][0] = pkp(xq0.w, xq1.w); acc[3][1] = pkp(xq2.w, xq3.w);

            {   // STS chunk0 (duplicated pairs)
                float* d0 = sz + kkt * 128 + 2 * r8;
                *(float4*)(d0)      = make_float4(s0.x, s0.x, s0.y, s0.y);
                *(float4*)(d0 + 4)  = make_float4(s0.z, s0.z, s0.w, s0.w);
                *(float4*)(d0 + 8)  = make_float4(s1.x, s1.x, s1.y, s1.y);
                *(float4*)(d0 + 12) = make_float4(s1.z, s1.z, s1.w, s1.w);
            }
            __syncthreads();

            for (int c = 0; c < 16; c++) {
                if (c < 15) {
                    const float* sn = hbase + (size_t)((c + 1) * 32 + kkt) * B_ + r8;
                    s0 = __ldcg((const float4*)sn);
                    s1 = __ldcg((const float4*)(sn + 4));
                }
                const float* szc = sz + (c & 1) * 4096;
                const int kb = c * 32;
#pragma unroll 8
                for (int kk = 0; kk < 32; kk++) {
                    const float* zr = szc + kk * 128 + 8 * ty;
                    ulonglong2 zA = *(const ulonglong2*)zr;
                    ulonglong2 zB = *(const ulonglong2*)(zr + 4);
                    ulonglong2 wq = *(const ulonglong2*)&sw[(kb + kk) * 64 + 4 * tx];
                    fma2(acc[0][0], zA.x, wq.x); fma2(acc[0][1], zA.x, wq.y);
                    fma2(acc[1][0], zA.y, wq.x); fma2(acc[1][1], zA.y, wq.y);
                    fma2(acc[2][0], zB.x, wq.x); fma2(acc[2][1], zB.x, wq.y);
                    fma2(acc[3][0], zB.y, wq.x); fma2(acc[3][1], zB.y, wq.y);
                }
                if (c < 15) {
                    float* dn = sz + ((c + 1) & 1) * 4096 + kkt * 128 + 2 * r8;
                    *(float4*)(dn)      = make_float4(s0.x, s0.x, s0.y, s0.y);
                    *(float4*)(dn + 4)  = make_float4(s0.z, s0.z, s0.w, s0.w);
                    *(float4*)(dn + 8)  = make_float4(s1.x, s1.x, s1.y, s1.y);
                    *(float4*)(dn + 12) = make_float4(s1.z, s1.z, s1.w, s1.w);
                }
                __syncthreads();
            }
            // epilogue: gates + state update (per-row activity)
#pragma unroll
            for (int r = 0; r < 4; r++) {
                float2 fi = unpk(acc[r][0]);
                float2 co = unpk(acc[r][1]);
                if (t < len[r]) {
                    float f = sigm(fi.x), ii = sigm(fi.y);
                    float g = tanhf(co.x), o = sigm(co.y);
                    cc[r] = f * cc[r] + ii * g;
                    hh[r] = o * tanhf(cc[r]);
                }
            }
            float* hdst = g_hbuf + ((t + 1) & 1) * HB + (size_t)u * B_ + b0 + 4 * ty;
            *(float4*)hdst = make_float4(hh[0], hh[1], hh[2], hh[3]);
            float* hsd = g_hs + ((size_t)t * H_ + u) * B_ + b0 + 4 * ty;
            if (t < len[3]) {                   // len sorted desc within thread
                *(float4*)hsd = make_float4(hh[0], hh[1], hh[2], hh[3]);
            } else {
#pragma unroll
                for (int r = 0; r < 4; r++) if (t < len[r]) hsd[r] = hh[r];
            }
        } else if (t == tile_len) {
            // one extra publish so BOTH h buffers hold the frozen h
            float* hdst = g_hbuf + ((t + 1) & 1) * HB + (size_t)u * B_ + b0 + 4 * ty;
            *(float4*)hdst = make_float4(hh[0], hh[1], hh[2], hh[3]);
        }

        // ---- software grid barrier ----
        __threadfence();
        __syncthreads();
        if (tid == 0) vf[bid] = (unsigned)(t + 1);
        if (bid == 0) {
            if (tid < NBLK) { while (vf[tid] < (unsigned)(t + 1)) __nanosleep(20); }
            __syncthreads();
            if (tid == 0) { __threadfence(); *vrel = (unsigned)(t + 1); }
        } else {
            if (tid == 0) { while (*vrel < (unsigned)(t + 1)) __nanosleep(20); }
            __syncthreads();
        }
    }
}

// ---------------- output GEMM: out[b][t][:] = hs[t][:][b] . W_lin + b_lin -------
__global__ void out_gemm(const float* __restrict__ Wl,
                         const float* __restrict__ bl,
                         float* __restrict__ out,
                         const int* __restrict__ seq)
{
    const int t  = blockIdx.x;
    const int b0 = blockIdx.y * 64;
    const int tid = threadIdx.x;
    const int bg  = tid >> 4;        // 4 batch rows each
    const int eg  = tid & 15;        // 8 e cols each

    if (t >= __ldg(&seq[b0])) {      // fully masked tile -> out = b_lin
#pragma unroll
        for (int u = 0; u < 4; u++) {
            int b = b0 + bg * 4 + u;
#pragma unroll
            for (int j = 0; j < 8; j++) {
                int e = eg * 8 + j;
                out[((size_t)b * T_ + t) * E_ + e] = bl[e];
            }
        }
        return;
    }

    __shared__ float sa[16][64];
    __shared__ float sb[16][128];
    float acc[4][8];
#pragma unroll
    for (int u = 0; u < 4; u++)
#pragma unroll
        for (int j = 0; j < 8; j++) acc[u][j] = 0.0f;

    for (int k0 = 0; k0 < H_; k0 += 16) {
        for (int i = tid; i < 16 * 64; i += 256) {
            int kk = i >> 6, bb = i & 63;
            sa[kk][bb] = g_hs[((size_t)t * H_ + k0 + kk) * B_ + b0 + bb];
        }
        for (int i = tid; i < 16 * 128; i += 256) {
            int kk = i >> 7, ee = i & 127;
            sb[kk][ee] = Wl[(k0 + kk) * E_ + ee];
        }
        __syncthreads();
#pragma unroll
        for (int kk = 0; kk < 16; kk++) {
            float av[4], wv[8];
#pragma unroll
            for (int u = 0; u < 4; u++) av[u] = sa[kk][bg * 4 + u];
#pragma unroll
            for (int j = 0; j < 8; j++) wv[j] = sb[kk][eg * 8 + j];
#pragma unroll
            for (int u = 0; u < 4; u++)
#pragma unroll
                for (int j = 0; j < 8; j++) acc[u][j] += av[u] * wv[j];
        }
        __syncthreads();
    }
#pragma unroll
    for (int u = 0; u < 4; u++) {
        int b = b0 + bg * 4 + u;
#pragma unroll
        for (int j = 0; j < 8; j++) {
            int e = eg * 8 + j;
            out[((size_t)b * T_ + t) * E_ + e] = acc[u][j] + bl[e];
        }
    }
}

// ---------------- launch --------------------------------------------------------
extern "C" void kernel_launch(void* const* d_in, const int* in_sizes, int n_in,
                              void* d_out, int out_size)
{
    const float* x1 = (const float*)d_in[0];
    const float* x2 = (const float*)d_in[1];
    const int*   sq = (const int*)  d_in[2];
    const float* Wf = (const float*)d_in[3];
    const float* bf = (const float*)d_in[4];
    const float* Wi = (const float*)d_in[5];
    const float* bi = (const float*)d_in[6];
    const float* Wc = (const float*)d_in[7];
    const float* bc = (const float*)d_in[8];
    const float* Wo = (const float*)d_in[9];
    const float* bo = (const float*)d_in[10];
    const float* Wa = (const float*)d_in[11];
    const float* Wl = (const float*)d_in[12];
    const float* bl = (const float*)d_in[13];
    float* out = (float*)d_out;

    const int SMEM_LSTM = (H_ * 64 + 2 * 32 * 128) * 4;   // 160 KB
    static int attr_done = 0;
    if (!attr_done) {
        cudaFuncSetAttribute(lstm_persist,
                             cudaFuncAttributeMaxDynamicSharedMemorySize, SMEM_LSTM);
        attr_done = 1;
    }

    reset_kernel<<<65536, 256>>>();
    weight_prep<<<6144, 256>>>(Wf, bf, Wi, bi, Wc, bc, Wo, bo);
    transpose_x1<<<dim3(E_ / 32, B_ / 32, T_), dim3(32, 8)>>>(x1, sq);
    attn_ctx<<<(B_ * T_) / 8, 256>>>(x2, Wa, sq);
    xpart_gemm<<<dim3(32, 4, T_), 256>>>(sq);
    lstm_persist<<<NBLK, 256, SMEM_LSTM>>>(sq);
    out_gemm<<<dim3(T_, B_ / 64), 256>>>(Wl, bl, out, sq);
}